// round 3
// baseline (speedup 1.0000x reference)
#include <cuda_runtime.h>
#include <cstdint>

#define EPS_IN 1e-5f

// Scratch for instance-norm statistics: sum and sum-of-squares per (scale,b,o).
// __device__ globals (allocation-free per harness rules).
__device__ float g_sum[5][16][128];
__device__ float g_sqs[5][16][128];

__global__ void zero_stats_kernel() {
    int i = blockIdx.x * blockDim.x + threadIdx.x;
    if (i < 5 * 16 * 128) {
        (&g_sum[0][0][0])[i] = 0.0f;
        (&g_sqs[0][0][0])[i] = 0.0f;
    }
}

// y[b,o,hw] = sum_c w[b,o,c] * x[b,c,hw]
// Block: all O=128 outputs for a THW-wide tile of HW, one batch b.
// 256 threads = 16 o-groups (8 o each) x 16 hw-groups (THW/16 hw each).
// Accumulators are packed f32x2 pairs driven by fma.rn.f32x2 (FFMA2).
template<int THW, bool STATS>
__global__ __launch_bounds__(256, 2)
void dynconv_kernel(const float* __restrict__ x, const float* __restrict__ w,
                    float* __restrict__ y, int HW, int scale)
{
    constexpr int C = 128, O = 128, KC = 64;
    constexpr int HWT = THW / 16;   // hw elements per thread (8 or 4)
    constexpr int NP  = HWT / 2;    // f32x2 pairs per o-row (4 or 2)

    __shared__ __align__(16) float xs[KC][THW];
    __shared__ __align__(16) float ws[KC][O];   // transposed: ws[c][o]

    const int b    = blockIdx.y;
    const int hw0  = blockIdx.x * THW;
    const int tid  = threadIdx.x;
    const int oid  = tid >> 4;      // 0..15
    const int hwid = tid & 15;      // 0..15
    const int obase = oid * 8;
    const int hwb   = hwid * HWT;

    unsigned long long acc[8][NP];
    #pragma unroll
    for (int j = 0; j < 8; j++)
        #pragma unroll
        for (int p = 0; p < NP; p++) acc[j][p] = 0ull;

    const float* xb = x + (size_t)b * C * HW + hw0;
    const float* wb = w + (size_t)b * O * C;

    for (int kk = 0; kk < C; kk += KC) {
        // Load x chunk: KC x THW, vectorized, coalesced.
        {
            constexpr int TOT4 = KC * THW / 4;
            #pragma unroll
            for (int e4 = 0; e4 < TOT4 / 256; e4++) {
                int e  = (e4 * 256 + tid) * 4;
                int c  = e / THW;
                int hw = e % THW;
                float4 v = *reinterpret_cast<const float4*>(&xb[(size_t)(kk + c) * HW + hw]);
                *reinterpret_cast<float4*>(&xs[c][hw]) = v;
            }
        }
        // Load w chunk transposed: ws[c][o] = w[b][o][kk+c]. Coalesced f4 reads along c.
        {
            constexpr int TOT4 = KC * O / 4;
            #pragma unroll
            for (int e4 = 0; e4 < TOT4 / 256; e4++) {
                int e = (e4 * 256 + tid) * 4;
                int o = e / KC;
                int c = e % KC;
                float4 v = *reinterpret_cast<const float4*>(&wb[(size_t)o * C + kk + c]);
                ws[c + 0][o] = v.x; ws[c + 1][o] = v.y;
                ws[c + 2][o] = v.z; ws[c + 3][o] = v.w;
            }
        }
        __syncthreads();

        #pragma unroll 4
        for (int c = 0; c < KC; c++) {
            unsigned long long xp[NP];
            #pragma unroll
            for (int p = 0; p < NP; p++)
                xp[p] = *reinterpret_cast<const unsigned long long*>(&xs[c][hwb + 2 * p]);
            #pragma unroll
            for (int j = 0; j < 8; j++) {
                unsigned long long wpk;
                asm("mov.b64 %0, {%1, %1};" : "=l"(wpk)
                    : "r"(__float_as_uint(ws[c][obase + j])));
                #pragma unroll
                for (int p = 0; p < NP; p++)
                    asm("fma.rn.f32x2 %0, %1, %2, %0;"
                        : "+l"(acc[j][p]) : "l"(xp[p]), "l"(wpk));
            }
        }
        __syncthreads();
    }

    // Write results + per-(b,o) partial statistics.
    float* yb = y + (size_t)b * O * HW + hw0;
    #pragma unroll
    for (int j = 0; j < 8; j++) {
        const int o = obase + j;
        float vals[HWT];
        #pragma unroll
        for (int p = 0; p < NP; p++) {
            unsigned int lo, hi;
            asm("mov.b64 {%0, %1}, %2;" : "=r"(lo), "=r"(hi) : "l"(acc[j][p]));
            vals[2 * p]     = __uint_as_float(lo);
            vals[2 * p + 1] = __uint_as_float(hi);
        }
        #pragma unroll
        for (int p = 0; p < NP / 2; p++) {
            float4 v = make_float4(vals[4 * p], vals[4 * p + 1],
                                   vals[4 * p + 2], vals[4 * p + 3]);
            *reinterpret_cast<float4*>(&yb[(size_t)o * HW + hwb + 4 * p]) = v;
        }
        if (STATS) {
            float s = 0.0f, q = 0.0f;
            #pragma unroll
            for (int t = 0; t < HWT; t++) { s += vals[t]; q += vals[t] * vals[t]; }
            // Reduce across the 16 hw-threads of this o-group (they are 16
            // consecutive lanes; xor<=8 stays inside each 16-lane half).
            #pragma unroll
            for (int d = 8; d >= 1; d >>= 1) {
                s += __shfl_xor_sync(0xffffffff, s, d);
                q += __shfl_xor_sync(0xffffffff, q, d);
            }
            if (hwid == 0) {
                atomicAdd(&g_sum[scale][b][o], s);
                atomicAdd(&g_sqs[scale][b][o], q);
            }
        }
    }
}

// InstanceNorm: one block per (b,o) row; mean/var from scratch sums; in-place.
__global__ void norm_kernel(float* __restrict__ y, int HW, int scale, float invHW)
{
    const int row = blockIdx.x;          // b*128 + o
    const int b = row >> 7, o = row & 127;
    const float s = g_sum[scale][b][o];
    const float q = g_sqs[scale][b][o];
    const float m = s * invHW;
    const float var = q * invHW - m * m;
    const float rstd = rsqrtf(var + EPS_IN);

    float4* p = reinterpret_cast<float4*>(y + (size_t)row * HW);
    const int n4 = HW >> 2;
    for (int i = threadIdx.x; i < n4; i += blockDim.x) {
        float4 v = p[i];
        v.x = (v.x - m) * rstd; v.y = (v.y - m) * rstd;
        v.z = (v.z - m) * rstd; v.w = (v.w - m) * rstd;
        p[i] = v;
    }
}

extern "C" void kernel_launch(void* const* d_in, const int* in_sizes, int n_in,
                              void* d_out, int out_size)
{
    // metadata order: x1, l1fs, x2, l2fs, x3, l3fs, x4, l4fs, x5, l5fs
    const float* x[5]; const float* w[5];
    for (int i = 0; i < 5; i++) {
        x[i] = (const float*)d_in[2 * i];
        w[i] = (const float*)d_in[2 * i + 1];
    }
    float* out = (float*)d_out;
    const int HWs[5] = {128 * 128, 64 * 64, 32 * 32, 16 * 16, 8 * 8};
    size_t off[5]; size_t accum = 0;
    for (int i = 0; i < 5; i++) { off[i] = accum; accum += (size_t)16 * 128 * HWs[i]; }

    zero_stats_kernel<<<(5 * 16 * 128 + 255) / 256, 256>>>();

    dynconv_kernel<128, true ><<<dim3(HWs[0] / 128, 16), 256>>>(x[0], w[0], out + off[0], HWs[0], 0);
    dynconv_kernel<128, true ><<<dim3(HWs[1] / 128, 16), 256>>>(x[1], w[1], out + off[1], HWs[1], 1);
    dynconv_kernel<128, true ><<<dim3(HWs[2] / 128, 16), 256>>>(x[2], w[2], out + off[2], HWs[2], 2);
    dynconv_kernel<128, true ><<<dim3(HWs[3] / 128, 16), 256>>>(x[3], w[3], out + off[3], HWs[3], 3);
    dynconv_kernel< 64, false><<<dim3(HWs[4] /  64, 16), 256>>>(x[4], w[4], out + off[4], HWs[4], 4);

    for (int i = 0; i < 4; i++)
        norm_kernel<<<16 * 128, 256>>>(out + off[i], HWs[i], i, 1.0f / (float)HWs[i]);
}

// round 5
// speedup vs baseline: 1.8584x; 1.8584x over previous
#include <cuda_runtime.h>
#include <cuda_bf16.h>
#include <cstdint>

#define EPS_IN 1e-5f

// Instance-norm statistics scratch (allocation-free __device__ globals).
__device__ float g_sum[5][16][128];
__device__ float g_sqs[5][16][128];

__global__ void zero_stats_kernel() {
    int i = blockIdx.x * blockDim.x + threadIdx.x;
    if (i < 5 * 16 * 128) {
        (&g_sum[0][0][0])[i] = 0.0f;
        (&g_sqs[0][0][0])[i] = 0.0f;
    }
}

__device__ __forceinline__ uint32_t smem_u32(const void* p) {
    uint32_t a;
    asm("{ .reg .u64 t; cvta.to.shared.u64 t, %1; cvt.u32.u64 %0, t; }"
        : "=r"(a) : "l"(p));
    return a;
}

// hi/lo bf16 split of two adjacent floats -> packed bf16x2 words
__device__ __forceinline__ void split2(float f0, float f1, uint32_t& hp, uint32_t& lp) {
    __nv_bfloat16 h0 = __float2bfloat16(f0);
    __nv_bfloat16 h1 = __float2bfloat16(f1);
    __nv_bfloat16 l0 = __float2bfloat16(f0 - __bfloat162float(h0));
    __nv_bfloat16 l1 = __float2bfloat16(f1 - __bfloat162float(h1));
    hp = ((uint32_t)__bfloat16_as_ushort(h1) << 16) | __bfloat16_as_ushort(h0);
    lp = ((uint32_t)__bfloat16_as_ushort(l1) << 16) | __bfloat16_as_ushort(l0);
}

#define LDSM4(r, a)                                                          \
    asm volatile("ldmatrix.sync.aligned.m8n8.x4.shared.b16 {%0,%1,%2,%3}, [%4];" \
                 : "=r"((r)[0]), "=r"((r)[1]), "=r"((r)[2]), "=r"((r)[3]) : "r"(a))
#define LDSM4T(r, a)                                                         \
    asm volatile("ldmatrix.sync.aligned.m8n8.x4.trans.shared.b16 {%0,%1,%2,%3}, [%4];" \
                 : "=r"((r)[0]), "=r"((r)[1]), "=r"((r)[2]), "=r"((r)[3]) : "r"(a))
#define MMA_BF16(d, a, b0, b1)                                               \
    asm volatile("mma.sync.aligned.m16n8k16.row.col.f32.bf16.bf16.f32 "      \
                 "{%0,%1,%2,%3}, {%4,%5,%6,%7}, {%8,%9}, {%0,%1,%2,%3};"     \
                 : "+f"((d)[0]), "+f"((d)[1]), "+f"((d)[2]), "+f"((d)[3])    \
                 : "r"((a)[0]), "r"((a)[1]), "r"((a)[2]), "r"((a)[3]),       \
                   "r"(b0), "r"(b1))

// ---------------- warp-MMA dynconv ----------------
// Block = one batch b, one 64-wide hw tile, all O=128 outputs. K=128 one pass.
// fp32 emulated as bf16 hi/lo: D += Ah*Bh + Ah*Bl + Al*Bh (fp32 accum HMMA).
// Smem pitches padded (+8 elems = 16B) so ldmatrix row phases are conflict-free.
template<bool STATS>
__global__ __launch_bounds__(256, 2)
void dynconv_mma(const float* __restrict__ x, const float* __restrict__ w,
                 float* __restrict__ y, int HW, int scale)
{
    extern __shared__ __align__(16) __nv_bfloat16 sm[];
    constexpr int WP = 136;            // W row pitch (elems): 272B
    constexpr int XP = 72;             // X row pitch (elems): 144B
    constexpr int WHI = 0;
    constexpr int WLO = 128 * WP;      // 17408
    constexpr int XHI = 2 * 128 * WP;  // 34816
    constexpr int XLO = XHI + 128 * XP;

    const int tid  = threadIdx.x;
    const int lane = tid & 31, wid = tid >> 5;
    const int b    = blockIdx.y;
    const int hw0  = blockIdx.x * 64;

    const float* wb = w + (size_t)b * 128 * 128;
    const float* xb = x + (size_t)b * 128 * HW + hw0;

    // --- convert W[b]: 128x128 f32 -> hi/lo bf16, [o][k] layout ---
    #pragma unroll
    for (int i = 0; i < 16; i++) {
        int e = i * 256 + tid;                 // 4096 float4 tiles
        int o = e >> 5, q = e & 31;
        float4 v = *reinterpret_cast<const float4*>(&wb[o * 128 + 4 * q]);
        uint32_t h0, l0, h1, l1;
        split2(v.x, v.y, h0, l0);
        split2(v.z, v.w, h1, l1);
        *reinterpret_cast<uint2*>(&sm[WHI + o * WP + 4 * q]) = make_uint2(h0, h1);
        *reinterpret_cast<uint2*>(&sm[WLO + o * WP + 4 * q]) = make_uint2(l0, l1);
    }
    // --- convert X chunk: 128 x 64 f32 -> hi/lo bf16, [k][hw] layout ---
    #pragma unroll
    for (int i = 0; i < 8; i++) {
        int e = i * 256 + tid;                 // 2048 float4 tiles
        int k = e >> 4, q = e & 15;
        float4 v = *reinterpret_cast<const float4*>(&xb[(size_t)k * HW + 4 * q]);
        uint32_t h0, l0, h1, l1;
        split2(v.x, v.y, h0, l0);
        split2(v.z, v.w, h1, l1);
        *reinterpret_cast<uint2*>(&sm[XHI + k * XP + 4 * q]) = make_uint2(h0, h1);
        *reinterpret_cast<uint2*>(&sm[XLO + k * XP + 4 * q]) = make_uint2(l0, l1);
    }
    __syncthreads();

    // --- MMA: warp tile 32(o) x 32(hw); warps: 4 along o, 2 along hw ---
    const int mw = wid & 3;            // o tile: mw*32
    const int nw = wid >> 2;           // hw tile: nw*32
    float acc[2][4][4] = {};

    const uint32_t smb = smem_u32(sm);
    // A addrs (non-trans x4): row = tileRow + (lane&15), col16B = (lane>>4)*8
    const uint32_t arow = (uint32_t)(mw * 32 + (lane & 15));
    const uint32_t acol = (uint32_t)((lane >> 4) * 8);
    const uint32_t aoff0 = (arow * WP + acol) * 2;
    const uint32_t aoff1 = ((arow + 16) * WP + acol) * 2;
    // B addrs (trans x4): k = (lane&15), n = tileCol + (lane>>4)*8
    const uint32_t brow = (uint32_t)(lane & 15);
    const uint32_t bcol = (uint32_t)(nw * 32 + (lane >> 4) * 8);
    const uint32_t boff0 = (brow * XP + bcol) * 2;
    const uint32_t boff1 = (brow * XP + bcol + 16) * 2;

    #pragma unroll
    for (int k = 0; k < 8; k++) {
        const uint32_t ka = (uint32_t)(k * 16 * 2);       // A advances along k (cols)
        const uint32_t kb = (uint32_t)(k * 16 * XP * 2);  // B advances along k (rows)
        uint32_t ah[2][4], al[2][4], bh[2][4], bl[2][4];
        LDSM4 (ah[0], smb + 2 * WHI + aoff0 + ka);
        LDSM4 (ah[1], smb + 2 * WHI + aoff1 + ka);
        LDSM4 (al[0], smb + 2 * WLO + aoff0 + ka);
        LDSM4 (al[1], smb + 2 * WLO + aoff1 + ka);
        LDSM4T(bh[0], smb + 2 * XHI + boff0 + kb);
        LDSM4T(bh[1], smb + 2 * XHI + boff1 + kb);
        LDSM4T(bl[0], smb + 2 * XLO + boff0 + kb);
        LDSM4T(bl[1], smb + 2 * XLO + boff1 + kb);
        #pragma unroll
        for (int mi = 0; mi < 2; mi++)
            #pragma unroll
            for (int nj = 0; nj < 4; nj++) {
                const int g2 = nj >> 1, pr = (nj & 1) * 2;
                MMA_BF16(acc[mi][nj], ah[mi], bh[g2][pr], bh[g2][pr + 1]);
                MMA_BF16(acc[mi][nj], ah[mi], bl[g2][pr], bl[g2][pr + 1]);
                MMA_BF16(acc[mi][nj], al[mi], bh[g2][pr], bh[g2][pr + 1]);
            }
    }

    // --- epilogue: store y + fused per-(b,o) stats ---
    const int g  = lane >> 2;
    const int qn = lane & 3;
    float* yb = y + (size_t)b * 128 * HW + hw0;
    float srow[4] = {0, 0, 0, 0}, qrow[4] = {0, 0, 0, 0};

    #pragma unroll
    for (int mi = 0; mi < 2; mi++) {
        const int o0 = mw * 32 + mi * 16 + g;
        #pragma unroll
        for (int nj = 0; nj < 4; nj++) {
            const int hw = nw * 32 + nj * 8 + qn * 2;
            float c0 = acc[mi][nj][0], c1 = acc[mi][nj][1];
            float c2 = acc[mi][nj][2], c3 = acc[mi][nj][3];
            *reinterpret_cast<float2*>(&yb[(size_t)o0 * HW + hw])       = make_float2(c0, c1);
            *reinterpret_cast<float2*>(&yb[(size_t)(o0 + 8) * HW + hw]) = make_float2(c2, c3);
            if (STATS) {
                srow[mi * 2 + 0] += c0 + c1;         qrow[mi * 2 + 0] += c0 * c0 + c1 * c1;
                srow[mi * 2 + 1] += c2 + c3;         qrow[mi * 2 + 1] += c2 * c2 + c3 * c3;
            }
        }
    }
    if (STATS) {
        #pragma unroll
        for (int idx = 0; idx < 4; idx++) {
            float s = srow[idx], q = qrow[idx];
            s += __shfl_xor_sync(0xffffffff, s, 1);
            q += __shfl_xor_sync(0xffffffff, q, 1);
            s += __shfl_xor_sync(0xffffffff, s, 2);
            q += __shfl_xor_sync(0xffffffff, q, 2);
            if (qn == 0) {
                const int o = mw * 32 + (idx >> 1) * 16 + g + (idx & 1) * 8;
                atomicAdd(&g_sum[scale][b][o], s);
                atomicAdd(&g_sqs[scale][b][o], q);
            }
        }
    }
}

// InstanceNorm: one block per (b,o) row; in-place.
__global__ void norm_kernel(float* __restrict__ y, int HW, int scale, float invHW)
{
    const int row = blockIdx.x;
    const int b = row >> 7, o = row & 127;
    const float m = g_sum[scale][b][o] * invHW;
    const float var = g_sqs[scale][b][o] * invHW - m * m;
    const float rstd = rsqrtf(var + EPS_IN);

    float4* p = reinterpret_cast<float4*>(y + (size_t)row * HW);
    const int n4 = HW >> 2;
    for (int i = threadIdx.x; i < n4; i += blockDim.x) {
        float4 v = p[i];
        v.x = (v.x - m) * rstd; v.y = (v.y - m) * rstd;
        v.z = (v.z - m) * rstd; v.w = (v.w - m) * rstd;
        p[i] = v;
    }
}

extern "C" void kernel_launch(void* const* d_in, const int* in_sizes, int n_in,
                              void* d_out, int out_size)
{
    const float* x[5]; const float* w[5];
    for (int i = 0; i < 5; i++) {
        x[i] = (const float*)d_in[2 * i];
        w[i] = (const float*)d_in[2 * i + 1];
    }
    float* out = (float*)d_out;
    const int HWs[5] = {128 * 128, 64 * 64, 32 * 32, 16 * 16, 8 * 8};
    size_t off[5]; size_t accum = 0;
    for (int i = 0; i < 5; i++) { off[i] = accum; accum += (size_t)16 * 128 * HWs[i]; }

    // dynamic smem: (2*128*136 + 2*128*72) bf16 elems = 106496 B
    const int SMEM = (2 * 128 * 136 + 2 * 128 * 72) * 2;
    static bool attr_set = false;
    if (!attr_set) {
        cudaFuncSetAttribute(dynconv_mma<true >, cudaFuncAttributeMaxDynamicSharedMemorySize, SMEM);
        cudaFuncSetAttribute(dynconv_mma<false>, cudaFuncAttributeMaxDynamicSharedMemorySize, SMEM);
        attr_set = true;
    }

    zero_stats_kernel<<<(5 * 16 * 128 + 255) / 256, 256>>>();

    dynconv_mma<true ><<<dim3(HWs[0] / 64, 16), 256, SMEM>>>(x[0], w[0], out + off[0], HWs[0], 0);
    dynconv_mma<true ><<<dim3(HWs[1] / 64, 16), 256, SMEM>>>(x[1], w[1], out + off[1], HWs[1], 1);
    dynconv_mma<true ><<<dim3(HWs[2] / 64, 16), 256, SMEM>>>(x[2], w[2], out + off[2], HWs[2], 2);
    dynconv_mma<true ><<<dim3(HWs[3] / 64, 16), 256, SMEM>>>(x[3], w[3], out + off[3], HWs[3], 3);
    dynconv_mma<false><<<dim3(HWs[4] / 64, 16), 256, SMEM>>>(x[4], w[4], out + off[4], HWs[4], 4);

    for (int i = 0; i < 4; i++)
        norm_kernel<<<16 * 128, 256>>>(out + off[i], HWs[i], i, 1.0f / (float)HWs[i]);
}

// round 7
// speedup vs baseline: 1.8687x; 1.0055x over previous
#include <cuda_runtime.h>
#include <cuda_bf16.h>
#include <cstdint>

#define EPS_IN 1e-5f

// Instance-norm statistics scratch (allocation-free __device__ globals).
__device__ float g_sum[5][16][128];
__device__ float g_sqs[5][16][128];

__global__ void zero_stats_kernel() {
    int i = blockIdx.x * blockDim.x + threadIdx.x;
    if (i < 5 * 16 * 128) {
        (&g_sum[0][0][0])[i] = 0.0f;
        (&g_sqs[0][0][0])[i] = 0.0f;
    }
}

__device__ __forceinline__ uint32_t smem_u32(const void* p) {
    uint32_t a;
    asm("{ .reg .u64 t; cvta.to.shared.u64 t, %1; cvt.u32.u64 %0, t; }"
        : "=r"(a) : "l"(p));
    return a;
}

// hi/lo bf16 split of two adjacent floats -> packed bf16x2 words
__device__ __forceinline__ void split2(float f0, float f1, uint32_t& hp, uint32_t& lp) {
    __nv_bfloat16 h0 = __float2bfloat16(f0);
    __nv_bfloat16 h1 = __float2bfloat16(f1);
    __nv_bfloat16 l0 = __float2bfloat16(f0 - __bfloat162float(h0));
    __nv_bfloat16 l1 = __float2bfloat16(f1 - __bfloat162float(h1));
    hp = ((uint32_t)__bfloat16_as_ushort(h1) << 16) | __bfloat16_as_ushort(h0);
    lp = ((uint32_t)__bfloat16_as_ushort(l1) << 16) | __bfloat16_as_ushort(l0);
}

#define LDSM4(r, a)                                                          \
    asm volatile("ldmatrix.sync.aligned.m8n8.x4.shared.b16 {%0,%1,%2,%3}, [%4];" \
                 : "=r"((r)[0]), "=r"((r)[1]), "=r"((r)[2]), "=r"((r)[3]) : "r"(a))
#define LDSM4T(r, a)                                                         \
    asm volatile("ldmatrix.sync.aligned.m8n8.x4.trans.shared.b16 {%0,%1,%2,%3}, [%4];" \
                 : "=r"((r)[0]), "=r"((r)[1]), "=r"((r)[2]), "=r"((r)[3]) : "r"(a))
#define MMA_BF16(d, a, b0, b1)                                               \
    asm volatile("mma.sync.aligned.m16n8k16.row.col.f32.bf16.bf16.f32 "      \
                 "{%0,%1,%2,%3}, {%4,%5,%6,%7}, {%8,%9}, {%0,%1,%2,%3};"     \
                 : "+f"((d)[0]), "+f"((d)[1]), "+f"((d)[2]), "+f"((d)[3])    \
                 : "r"((a)[0]), "r"((a)[1]), "r"((a)[2]), "r"((a)[3]),       \
                   "r"(b0), "r"(b1))

// ---------------- warp-MMA dynconv ----------------
// Block = one batch b, one 64-wide hw tile, all O=128 outputs. K=128 one pass.
// fp32 emulated as bf16 hi/lo: D += Ah*Bh + Ah*Bl + Al*Bh (fp32 accum HMMA).
// Smem pitches padded (+8 elems = 16B) so ldmatrix row phases are conflict-free.
template<bool STATS>
__global__ __launch_bounds__(256, 2)
void dynconv_mma(const float* __restrict__ x, const float* __restrict__ w,
                 float* __restrict__ y, int HW, int scale)
{
    extern __shared__ __align__(16) __nv_bfloat16 sm[];
    constexpr int WP = 136;            // W row pitch (elems): 272B
    constexpr int XP = 72;             // X row pitch (elems): 144B
    constexpr int WHI = 0;
    constexpr int WLO = 128 * WP;      // 17408
    constexpr int XHI = 2 * 128 * WP;  // 34816
    constexpr int XLO = XHI + 128 * XP;

    const int tid  = threadIdx.x;
    const int lane = tid & 31, wid = tid >> 5;
    const int b    = blockIdx.y;
    const int hw0  = blockIdx.x * 64;

    const float* wb = w + (size_t)b * 128 * 128;
    const float* xb = x + (size_t)b * 128 * HW + hw0;

    // --- convert W[b]: 128x128 f32 -> hi/lo bf16, [o][k] layout ---
    #pragma unroll
    for (int i = 0; i < 16; i++) {
        int e = i * 256 + tid;                 // 4096 float4 tiles
        int o = e >> 5, q = e & 31;
        float4 v = *reinterpret_cast<const float4*>(&wb[o * 128 + 4 * q]);
        uint32_t h0, l0, h1, l1;
        split2(v.x, v.y, h0, l0);
        split2(v.z, v.w, h1, l1);
        *reinterpret_cast<uint2*>(&sm[WHI + o * WP + 4 * q]) = make_uint2(h0, h1);
        *reinterpret_cast<uint2*>(&sm[WLO + o * WP + 4 * q]) = make_uint2(l0, l1);
    }
    // --- convert X chunk: 128 x 64 f32 -> hi/lo bf16, [k][hw] layout ---
    #pragma unroll
    for (int i = 0; i < 8; i++) {
        int e = i * 256 + tid;                 // 2048 float4 tiles
        int k = e >> 4, q = e & 15;
        float4 v = *reinterpret_cast<const float4*>(&xb[(size_t)k * HW + 4 * q]);
        uint32_t h0, l0, h1, l1;
        split2(v.x, v.y, h0, l0);
        split2(v.z, v.w, h1, l1);
        *reinterpret_cast<uint2*>(&sm[XHI + k * XP + 4 * q]) = make_uint2(h0, h1);
        *reinterpret_cast<uint2*>(&sm[XLO + k * XP + 4 * q]) = make_uint2(l0, l1);
    }
    __syncthreads();

    // --- MMA: warp tile 32(o) x 32(hw); warps: 4 along o, 2 along hw ---
    const int mw = wid & 3;            // o tile: mw*32
    const int nw = wid >> 2;           // hw tile: nw*32
    float acc[2][4][4] = {};

    const uint32_t smb = smem_u32(sm);
    // A addrs (non-trans x4): row = tileRow + (lane&15), col16B = (lane>>4)*8
    const uint32_t arow = (uint32_t)(mw * 32 + (lane & 15));
    const uint32_t acol = (uint32_t)((lane >> 4) * 8);
    const uint32_t aoff0 = (arow * WP + acol) * 2;
    const uint32_t aoff1 = ((arow + 16) * WP + acol) * 2;
    // B addrs (trans x4): k = (lane&15), n = tileCol + (lane>>4)*8
    const uint32_t brow = (uint32_t)(lane & 15);
    const uint32_t bcol = (uint32_t)(nw * 32 + (lane >> 4) * 8);
    const uint32_t boff0 = (brow * XP + bcol) * 2;
    const uint32_t boff1 = (brow * XP + bcol + 16) * 2;

    #pragma unroll
    for (int k = 0; k < 8; k++) {
        const uint32_t ka = (uint32_t)(k * 16 * 2);       // A advances along k (cols)
        const uint32_t kb = (uint32_t)(k * 16 * XP * 2);  // B advances along k (rows)
        uint32_t ah[2][4], al[2][4], bh[2][4], bl[2][4];
        LDSM4 (ah[0], smb + 2 * WHI + aoff0 + ka);
        LDSM4 (ah[1], smb + 2 * WHI + aoff1 + ka);
        LDSM4 (al[0], smb + 2 * WLO + aoff0 + ka);
        LDSM4 (al[1], smb + 2 * WLO + aoff1 + ka);
        LDSM4T(bh[0], smb + 2 * XHI + boff0 + kb);
        LDSM4T(bh[1], smb + 2 * XHI + boff1 + kb);
        LDSM4T(bl[0], smb + 2 * XLO + boff0 + kb);
        LDSM4T(bl[1], smb + 2 * XLO + boff1 + kb);
        #pragma unroll
        for (int mi = 0; mi < 2; mi++)
            #pragma unroll
            for (int nj = 0; nj < 4; nj++) {
                const int g2 = nj >> 1, pr = (nj & 1) * 2;
                MMA_BF16(acc[mi][nj], ah[mi], bh[g2][pr], bh[g2][pr + 1]);
                MMA_BF16(acc[mi][nj], ah[mi], bl[g2][pr], bl[g2][pr + 1]);
                MMA_BF16(acc[mi][nj], al[mi], bh[g2][pr], bh[g2][pr + 1]);
            }
    }

    // --- epilogue: store y + fused per-(b,o) stats ---
    const int g  = lane >> 2;
    const int qn = lane & 3;
    float* yb = y + (size_t)b * 128 * HW + hw0;
    float srow[4] = {0, 0, 0, 0}, qrow[4] = {0, 0, 0, 0};

    #pragma unroll
    for (int mi = 0; mi < 2; mi++) {
        const int o0 = mw * 32 + mi * 16 + g;
        #pragma unroll
        for (int nj = 0; nj < 4; nj++) {
            const int hw = nw * 32 + nj * 8 + qn * 2;
            float c0 = acc[mi][nj][0], c1 = acc[mi][nj][1];
            float c2 = acc[mi][nj][2], c3 = acc[mi][nj][3];
            *reinterpret_cast<float2*>(&yb[(size_t)o0 * HW + hw])       = make_float2(c0, c1);
            *reinterpret_cast<float2*>(&yb[(size_t)(o0 + 8) * HW + hw]) = make_float2(c2, c3);
            if (STATS) {
                srow[mi * 2 + 0] += c0 + c1;         qrow[mi * 2 + 0] += c0 * c0 + c1 * c1;
                srow[mi * 2 + 1] += c2 + c3;         qrow[mi * 2 + 1] += c2 * c2 + c3 * c3;
            }
        }
    }
    if (STATS) {
        #pragma unroll
        for (int idx = 0; idx < 4; idx++) {
            float s = srow[idx], q = qrow[idx];
            s += __shfl_xor_sync(0xffffffff, s, 1);
            q += __shfl_xor_sync(0xffffffff, q, 1);
            s += __shfl_xor_sync(0xffffffff, s, 2);
            q += __shfl_xor_sync(0xffffffff, q, 2);
            if (qn == 0) {
                const int o = mw * 32 + (idx >> 1) * 16 + g + (idx & 1) * 8;
                atomicAdd(&g_sum[scale][b][o], s);
                atomicAdd(&g_sqs[scale][b][o], q);
            }
        }
    }
}

// InstanceNorm: one block per (b,o) row; in-place.
__global__ void norm_kernel(float* __restrict__ y, int HW, int scale, float invHW)
{
    const int row = blockIdx.x;
    const int b = row >> 7, o = row & 127;
    const float m = g_sum[scale][b][o] * invHW;
    const float var = g_sqs[scale][b][o] * invHW - m * m;
    const float rstd = rsqrtf(var + EPS_IN);

    float4* p = reinterpret_cast<float4*>(y + (size_t)row * HW);
    const int n4 = HW >> 2;
    for (int i = threadIdx.x; i < n4; i += blockDim.x) {
        float4 v = p[i];
        v.x = (v.x - m) * rstd; v.y = (v.y - m) * rstd;
        v.z = (v.z - m) * rstd; v.w = (v.w - m) * rstd;
        p[i] = v;
    }
}

extern "C" void kernel_launch(void* const* d_in, const int* in_sizes, int n_in,
                              void* d_out, int out_size)
{
    const float* x[5]; const float* w[5];
    for (int i = 0; i < 5; i++) {
        x[i] = (const float*)d_in[2 * i];
        w[i] = (const float*)d_in[2 * i + 1];
    }
    float* out = (float*)d_out;
    const int HWs[5] = {128 * 128, 64 * 64, 32 * 32, 16 * 16, 8 * 8};
    size_t off[5]; size_t accum = 0;
    for (int i = 0; i < 5; i++) { off[i] = accum; accum += (size_t)16 * 128 * HWs[i]; }

    // dynamic smem: (2*128*136 + 2*128*72) bf16 elems = 106496 B
    const int SMEM = (2 * 128 * 136 + 2 * 128 * 72) * 2;
    static bool attr_set = false;
    if (!attr_set) {
        cudaFuncSetAttribute(dynconv_mma<true >, cudaFuncAttributeMaxDynamicSharedMemorySize, SMEM);
        cudaFuncSetAttribute(dynconv_mma<false>, cudaFuncAttributeMaxDynamicSharedMemorySize, SMEM);
        attr_set = true;
    }

    zero_stats_kernel<<<(5 * 16 * 128 + 255) / 256, 256>>>();

    dynconv_mma<true ><<<dim3(HWs[0] / 64, 16), 256, SMEM>>>(x[0], w[0], out + off[0], HWs[0], 0);
    dynconv_mma<true ><<<dim3(HWs[1] / 64, 16), 256, SMEM>>>(x[1], w[1], out + off[1], HWs[1], 1);
    dynconv_mma<true ><<<dim3(HWs[2] / 64, 16), 256, SMEM>>>(x[2], w[2], out + off[2], HWs[2], 2);
    dynconv_mma<true ><<<dim3(HWs[3] / 64, 16), 256, SMEM>>>(x[3], w[3], out + off[3], HWs[3], 3);
    dynconv_mma<false><<<dim3(HWs[4] / 64, 16), 256, SMEM>>>(x[4], w[4], out + off[4], HWs[4], 4);

    for (int i = 0; i < 4; i++)
        norm_kernel<<<16 * 128, 256>>>(out + off[i], HWs[i], i, 1.0f / (float)HWs[i]);
}